// round 2
// baseline (speedup 1.0000x reference)
#include <cuda_runtime.h>
#include <cstdint>

// ---------------------------------------------------------------------------
// StateQueue: fused select/copy kernel.
//   Outputs (flattened f32, concatenated in reference-tuple order):
//     mq (B,QM,N,D) | pq (B,QP,NP,D) | eq (B,QP,D) | per (B,QM) |
//     mm (B,T-1,N)  | me (B,T-1,N,D) | pm (B,T-1,1) | pe (B,T-1,1,D)
//   Bool inputs are materialized by the harness as int32.
// ---------------------------------------------------------------------------

namespace sq {
constexpr int B = 16, N = 900, D = 256, QM = 4, QP = 4, NP = 6, T = 4;
constexpr int D4 = D / 4;      // 64 float4 per D row
constexpr int TM1 = T - 1;     // 3

// region sizes in float4 units
constexpr int R0 = B * QM * N * D4;     // mq   3,686,400
constexpr int R1 = B * QP * NP * D4;    // pq      24,576
constexpr int R2 = B * QP * D4;         // eq       4,096
constexpr int R3 = (B * QM) / 4;        // per         16
constexpr int R4 = (B * TM1 * N) / 4;   // mm      10,800
constexpr int R5 = B * TM1 * N * D4;    // me   2,764,800
constexpr int R6 = (B * TM1) / 4;       // pm          12
constexpr int R7 = B * TM1 * D4;        // pe       3,072

constexpr int E0 = R0;
constexpr int E1 = E0 + R1;
constexpr int E2 = E1 + R2;
constexpr int E3 = E2 + R3;
constexpr int E4 = E3 + R4;
constexpr int E5 = E4 + R5;
constexpr int E6 = E5 + R6;
constexpr int TOTAL4 = E6 + R7;         // 6,493,772 float4 = 25,975,088 floats
}  // namespace sq

__global__ void __launch_bounds__(256)
state_queue_kernel(
    const float4* __restrict__ motion_query,   // (B,N,D)
    const float4* __restrict__ plan_query,     // (B,NP,D)
    const float4* __restrict__ ego_status,     // (B,D)
    const float4* __restrict__ motion_queue,   // (B,QM,N,D)
    const float4* __restrict__ plan_queue,     // (B,QP,NP,D)
    const float4* __restrict__ ego_queue,      // (B,QP,D)
    const int*    __restrict__ period,         // (B,QM)  int32
    const int*    __restrict__ mask,           // (B,)    bool as int32
    const float4* __restrict__ temp_embed,     // (B,N,T,D)
    const int*    __restrict__ temp_mask,      // (B,N,T) bool as int32
    const float4* __restrict__ ego_embed,      // (B,1,T,D)
    const int*    __restrict__ ego_mask,       // (B,1,T) bool as int32
    float4* __restrict__ out)
{
    using namespace sq;
    const int i = blockIdx.x * blockDim.x + threadIdx.x;
    if (i >= TOTAL4) return;

    if (i < E0) {
        // ---- mq[b,q,n,d] = reset ? motion_query[b,n,d] : motion_queue[b,q,n,d]
        const int d4 = i & (D4 - 1);
        const int r  = i >> 6;          // (b*QM + q)*N + n
        const int n  = r % N;
        const int bq = r / N;
        const int b  = bq >> 2;
        const bool reset = (mask[b] == 0);
        out[i] = reset ? motion_query[(b * N + n) * D4 + d4]
                       : motion_queue[i];
    } else if (i < E1) {
        // ---- pq
        const int rel = i - E0;
        const int d4 = rel & (D4 - 1);
        const int r  = rel >> 6;        // (b*QP + q)*NP + np
        const int np = r % NP;
        const int bq = r / NP;
        const int b  = bq >> 2;
        const bool reset = (mask[b] == 0);
        out[i] = reset ? plan_query[(b * NP + np) * D4 + d4]
                       : plan_queue[rel];
    } else if (i < E2) {
        // ---- eq
        const int rel = i - E1;
        const int d4 = rel & (D4 - 1);
        const int r  = rel >> 6;        // b*QP + q
        const int b  = r >> 2;
        const bool reset = (mask[b] == 0);
        out[i] = reset ? ego_status[b * D4 + d4]
                       : ego_queue[rel];
    } else if (i < E3) {
        // ---- per[b,q] = reset ? 0 : period[b,q]   (4 scalars per float4)
        const int rel = i - E2;
        float4 v;
        float* vp = &v.x;
        #pragma unroll
        for (int j = 0; j < 4; j++) {
            const int e = rel * 4 + j;  // b*QM + q
            const int b = e >> 2;
            vp[j] = (mask[b] == 0) ? 0.0f : (float)period[e];
        }
        out[i] = v;
    } else if (i < E4) {
        // ---- mm_out[b,t,n] = temp_mask[b,n,t]   (4 scalars per float4)
        const int rel = i - E3;
        float4 v;
        float* vp = &v.x;
        #pragma unroll
        for (int j = 0; j < 4; j++) {
            const int e  = rel * 4 + j;      // (b*TM1 + t)*N + n
            const int n  = e % N;
            const int bt = e / N;
            const int t  = bt % TM1;
            const int b  = bt / TM1;
            vp[j] = (temp_mask[(b * N + n) * T + t] != 0) ? 1.0f : 0.0f;
        }
        out[i] = v;
    } else if (i < E5) {
        // ---- me_out[b,t,n,d] = temp_embed[b,n,t,d]
        const int rel = i - E4;
        const int d4 = rel & (D4 - 1);
        const int r  = rel >> 6;        // (b*TM1 + t)*N + n
        const int n  = r % N;
        const int bt = r / N;
        const int t  = bt % TM1;
        const int b  = bt / TM1;
        out[i] = temp_embed[((b * N + n) * T + t) * D4 + d4];
    } else if (i < E6) {
        // ---- pm_out[b,t,0] = ego_mask[b,0,t]
        const int rel = i - E5;
        float4 v;
        float* vp = &v.x;
        #pragma unroll
        for (int j = 0; j < 4; j++) {
            const int e = rel * 4 + j;  // b*TM1 + t
            const int t = e % TM1;
            const int b = e / TM1;
            vp[j] = (ego_mask[b * T + t] != 0) ? 1.0f : 0.0f;
        }
        out[i] = v;
    } else {
        // ---- pe_out[b,t,0,d]
        const int rel = i - E6;
        const int d4 = rel & (D4 - 1);
        const int r  = rel >> 6;        // b*TM1 + t
        const int t  = r % TM1;
        const int b  = r / TM1;

        // ego_mask is (B,1,T) int32: 64 words. pm slice = t in [0, T-2].
        bool any_flag = false;
        #pragma unroll
        for (int bb = 0; bb < B; bb++) {
            #pragma unroll
            for (int tt = 0; tt < TM1; tt++) {
                any_flag |= (ego_mask[bb * T + tt] != 0);
            }
        }
        const bool m0 = (ego_mask[b * T + 0] != 0);
        const bool m1 = (ego_mask[b * T + 1] != 0);
        const bool m2 = (ego_mask[b * T + 2] != 0);
        const bool all_true = m0 && m1 && m2;
        // argmin over bools: first False index; 0 if all True
        const int first_false = !m0 ? 0 : (!m1 ? 1 : (!m2 ? 2 : 0));

        const bool overwrite = all_true || (t < first_false);
        int sel_t = t;
        if (any_flag && overwrite) sel_t = all_true ? (T - 1) : first_false;

        out[i] = ego_embed[(b * T + sel_t) * D4 + d4];
    }
}

extern "C" void kernel_launch(void* const* d_in, const int* in_sizes, int n_in,
                              void* d_out, int out_size) {
    (void)in_sizes; (void)n_in; (void)out_size;
    const float4* motion_query = (const float4*)d_in[0];
    const float4* plan_query   = (const float4*)d_in[1];
    const float4* ego_status   = (const float4*)d_in[2];
    const float4* motion_queue = (const float4*)d_in[3];
    const float4* plan_queue   = (const float4*)d_in[4];
    const float4* ego_queue    = (const float4*)d_in[5];
    const int*    period       = (const int*)d_in[6];
    const int*    mask         = (const int*)d_in[7];
    const float4* temp_embed   = (const float4*)d_in[8];
    const int*    temp_mask    = (const int*)d_in[9];
    const float4* ego_embed    = (const float4*)d_in[10];
    const int*    ego_mask     = (const int*)d_in[11];

    const int threads = 256;
    const int blocks  = (sq::TOTAL4 + threads - 1) / threads;
    state_queue_kernel<<<blocks, threads>>>(
        motion_query, plan_query, ego_status, motion_queue, plan_queue,
        ego_queue, period, mask, temp_embed, temp_mask, ego_embed, ego_mask,
        (float4*)d_out);
}

// round 8
// speedup vs baseline: 1.0580x; 1.0580x over previous
#include <cuda_runtime.h>
#include <cstdint>

// ---------------------------------------------------------------------------
// StateQueue: fused select/copy kernel, 2 float4 per thread for MLP=2.
//   Outputs (flattened f32, concatenated in reference-tuple order):
//     mq (B,QM,N,D) | pq (B,QP,NP,D) | eq (B,QP,D) | per (B,QM) |
//     mm (B,T-1,N)  | me (B,T-1,N,D) | pm (B,T-1,1) | pe (B,T-1,1,D)
//   Bool inputs are materialized by the harness as int32.
// ---------------------------------------------------------------------------

namespace sq {
constexpr int B = 16, N = 900, D = 256, QM = 4, QP = 4, NP = 6, T = 4;
constexpr int D4 = D / 4;      // 64 float4 per D row
constexpr int TM1 = T - 1;     // 3

// region sizes in float4 units
constexpr int R0 = B * QM * N * D4;     // mq   3,686,400
constexpr int R1 = B * QP * NP * D4;    // pq      24,576
constexpr int R2 = B * QP * D4;         // eq       4,096
constexpr int R3 = (B * QM) / 4;        // per         16
constexpr int R4 = (B * TM1 * N) / 4;   // mm      10,800
constexpr int R5 = B * TM1 * N * D4;    // me   2,764,800
constexpr int R6 = (B * TM1) / 4;       // pm          12
constexpr int R7 = B * TM1 * D4;        // pe       3,072

constexpr int E0 = R0;
constexpr int E1 = E0 + R1;
constexpr int E2 = E1 + R2;
constexpr int E3 = E2 + R3;
constexpr int E4 = E3 + R4;
constexpr int E5 = E4 + R5;
constexpr int E6 = E5 + R6;
constexpr int TOTAL4 = E6 + R7;         // 6,493,772 float4 (even)
}  // namespace sq

struct SqArgs {
    const float4* __restrict__ motion_query;   // (B,N,D)
    const float4* __restrict__ plan_query;     // (B,NP,D)
    const float4* __restrict__ ego_status;     // (B,D)
    const float4* __restrict__ motion_queue;   // (B,QM,N,D)
    const float4* __restrict__ plan_queue;     // (B,QP,NP,D)
    const float4* __restrict__ ego_queue;      // (B,QP,D)
    const int*    __restrict__ period;         // (B,QM)  int32
    const int*    __restrict__ mask;           // (B,)    bool as int32
    const float4* __restrict__ temp_embed;     // (B,N,T,D)
    const int*    __restrict__ temp_mask;      // (B,N,T) bool as int32
    const float4* __restrict__ ego_embed;      // (B,1,T,D)
    const int*    __restrict__ ego_mask;       // (B,1,T) bool as int32
};

__device__ __forceinline__ float4 sq_fetch(int i, const SqArgs& a)
{
    using namespace sq;
    if (i < E0) {
        // ---- mq[b,q,n,d] = reset ? motion_query[b,n,d] : motion_queue[b,q,n,d]
        const int d4 = i & (D4 - 1);
        const int r  = i >> 6;          // (b*QM + q)*N + n
        const int n  = r % N;
        const int bq = r / N;
        const int b  = bq >> 2;
        const bool reset = (a.mask[b] == 0);
        return reset ? a.motion_query[(b * N + n) * D4 + d4]
                     : a.motion_queue[i];
    } else if (i < E1) {
        // ---- pq
        const int rel = i - E0;
        const int d4 = rel & (D4 - 1);
        const int r  = rel >> 6;        // (b*QP + q)*NP + np
        const int np = r % NP;
        const int bq = r / NP;
        const int b  = bq >> 2;
        const bool reset = (a.mask[b] == 0);
        return reset ? a.plan_query[(b * NP + np) * D4 + d4]
                     : a.plan_queue[rel];
    } else if (i < E2) {
        // ---- eq
        const int rel = i - E1;
        const int d4 = rel & (D4 - 1);
        const int r  = rel >> 6;        // b*QP + q
        const int b  = r >> 2;
        const bool reset = (a.mask[b] == 0);
        return reset ? a.ego_status[b * D4 + d4]
                     : a.ego_queue[rel];
    } else if (i < E3) {
        // ---- per[b,q] = reset ? 0 : period[b,q]   (4 scalars per float4)
        const int rel = i - E2;
        float4 v;
        float* vp = &v.x;
        #pragma unroll
        for (int j = 0; j < 4; j++) {
            const int e = rel * 4 + j;  // b*QM + q
            const int b = e >> 2;
            vp[j] = (a.mask[b] == 0) ? 0.0f : (float)a.period[e];
        }
        return v;
    } else if (i < E4) {
        // ---- mm_out[b,t,n] = temp_mask[b,n,t]   (4 scalars per float4)
        const int rel = i - E3;
        float4 v;
        float* vp = &v.x;
        #pragma unroll
        for (int j = 0; j < 4; j++) {
            const int e  = rel * 4 + j;      // (b*TM1 + t)*N + n
            const int n  = e % N;
            const int bt = e / N;
            const int t  = bt % TM1;
            const int b  = bt / TM1;
            vp[j] = (a.temp_mask[(b * N + n) * T + t] != 0) ? 1.0f : 0.0f;
        }
        return v;
    } else if (i < E5) {
        // ---- me_out[b,t,n,d] = temp_embed[b,n,t,d]
        const int rel = i - E4;
        const int d4 = rel & (D4 - 1);
        const int r  = rel >> 6;        // (b*TM1 + t)*N + n
        const int n  = r % N;
        const int bt = r / N;
        const int t  = bt % TM1;
        const int b  = bt / TM1;
        return a.temp_embed[((b * N + n) * T + t) * D4 + d4];
    } else if (i < E6) {
        // ---- pm_out[b,t,0] = ego_mask[b,0,t]
        const int rel = i - E5;
        float4 v;
        float* vp = &v.x;
        #pragma unroll
        for (int j = 0; j < 4; j++) {
            const int e = rel * 4 + j;  // b*TM1 + t
            const int t = e % TM1;
            const int b = e / TM1;
            vp[j] = (a.ego_mask[b * T + t] != 0) ? 1.0f : 0.0f;
        }
        return v;
    } else {
        // ---- pe_out[b,t,0,d]
        const int rel = i - E6;
        const int d4 = rel & (D4 - 1);
        const int r  = rel >> 6;        // b*TM1 + t
        const int t  = r % TM1;
        const int b  = r / TM1;

        // ego_mask is (B,1,T) int32: 64 words. pm slice = t in [0, T-2].
        bool any_flag = false;
        #pragma unroll
        for (int bb = 0; bb < B; bb++) {
            #pragma unroll
            for (int tt = 0; tt < TM1; tt++) {
                any_flag |= (a.ego_mask[bb * T + tt] != 0);
            }
        }
        const bool m0 = (a.ego_mask[b * T + 0] != 0);
        const bool m1 = (a.ego_mask[b * T + 1] != 0);
        const bool m2 = (a.ego_mask[b * T + 2] != 0);
        const bool all_true = m0 && m1 && m2;
        // argmin over bools: first False index; 0 if all True
        const int first_false = !m0 ? 0 : (!m1 ? 1 : (!m2 ? 2 : 0));

        const bool overwrite = all_true || (t < first_false);
        int sel_t = t;
        if (any_flag && overwrite) sel_t = all_true ? (T - 1) : first_false;

        return a.ego_embed[(b * T + sel_t) * D4 + d4];
    }
}

__global__ void __launch_bounds__(256)
state_queue_kernel(SqArgs a, float4* __restrict__ out)
{
    using namespace sq;
    const int i0 = (blockIdx.x * blockDim.x + threadIdx.x) * 2;
    if (i0 + 1 < TOTAL4) {
        // Two independent fetches: compiler hoists both LDGs before the STGs
        // (out is restrict-disjoint from all inputs) -> MLP=2 per thread.
        const float4 v0 = sq_fetch(i0,     a);
        const float4 v1 = sq_fetch(i0 + 1, a);
        out[i0]     = v0;
        out[i0 + 1] = v1;
    } else if (i0 < TOTAL4) {
        out[i0] = sq_fetch(i0, a);
    }
}

extern "C" void kernel_launch(void* const* d_in, const int* in_sizes, int n_in,
                              void* d_out, int out_size) {
    (void)in_sizes; (void)n_in; (void)out_size;
    SqArgs a;
    a.motion_query = (const float4*)d_in[0];
    a.plan_query   = (const float4*)d_in[1];
    a.ego_status   = (const float4*)d_in[2];
    a.motion_queue = (const float4*)d_in[3];
    a.plan_queue   = (const float4*)d_in[4];
    a.ego_queue    = (const float4*)d_in[5];
    a.period       = (const int*)d_in[6];
    a.mask         = (const int*)d_in[7];
    a.temp_embed   = (const float4*)d_in[8];
    a.temp_mask    = (const int*)d_in[9];
    a.ego_embed    = (const float4*)d_in[10];
    a.ego_mask     = (const int*)d_in[11];

    const int threads = 256;
    const int pairs   = (sq::TOTAL4 + 1) / 2;
    const int blocks  = (pairs + threads - 1) / threads;
    state_queue_kernel<<<blocks, threads>>>(a, (float4*)d_out);
}